// round 14
// baseline (speedup 1.0000x reference)
#include <cuda_runtime.h>
#include <cuda_fp16.h>
#include <math.h>
#include <stdint.h>

#define NT 8
#define NN 50000
#define NE 800000
#define HD 128
#define NL 2

__device__ __forceinline__ uint32_t smem_u32(const void* p) {
    uint32_t a;
    asm("{ .reg .u64 t; cvta.to.shared.u64 t, %1; cvt.u32.u64 %0, t; }" : "=r"(a) : "l"(p));
    return a;
}
__device__ __forceinline__ float sigf(float x) { return 1.f / (1.f + __expf(-x)); }

__device__ __forceinline__ void mma16816(float* d, const uint32_t* a, const uint32_t* b) {
    asm volatile("mma.sync.aligned.m16n8k16.row.col.f32.f16.f16.f32 "
        "{%0,%1,%2,%3}, {%4,%5,%6,%7}, {%8,%9}, {%0,%1,%2,%3};"
        : "+f"(d[0]), "+f"(d[1]), "+f"(d[2]), "+f"(d[3])
        : "r"(a[0]), "r"(a[1]), "r"(a[2]), "r"(a[3]), "r"(b[0]), "r"(b[1]));
}
__device__ __forceinline__ void ldsm4(uint32_t* r, uint32_t addr) {
    asm volatile("ldmatrix.sync.aligned.m8n8.x4.shared.b16 {%0,%1,%2,%3}, [%4];"
        : "=r"(r[0]), "=r"(r[1]), "=r"(r[2]), "=r"(r[3]) : "r"(addr));
}
__device__ __forceinline__ void cpa16(uint32_t dst, const void* src, bool pred) {
    asm volatile("cp.async.cg.shared.global [%0], [%1], 16, %2;"
        :: "r"(dst), "l"(__cvta_generic_to_global(src)), "r"(pred ? 16 : 0) : "memory");
}
#define CP_COMMIT() asm volatile("cp.async.commit_group;" ::: "memory")
#define CP_WAIT1()  asm volatile("cp.async.wait_group 1;" ::: "memory")

__device__ __forceinline__ uint2 packh4(float4 a) {
    __half2 p0 = __float22half2_rn(make_float2(a.x, a.y));
    __half2 p1 = __float22half2_rn(make_float2(a.z, a.w));
    uint2 r;
    r.x = *(uint32_t*)&p0;
    r.y = *(uint32_t*)&p1;
    return r;
}
__device__ __forceinline__ void acc8(float* a, uint4 u, float w) {
    float2 f;
    f = __half22float2(*(__half2*)&u.x); a[0] += w * f.x; a[1] += w * f.y;
    f = __half22float2(*(__half2*)&u.y); a[2] += w * f.x; a[3] += w * f.y;
    f = __half22float2(*(__half2*)&u.z); a[4] += w * f.x; a[5] += w * f.y;
    f = __half22float2(*(__half2*)&u.w); a[6] += w * f.x; a[7] += w * f.y;
}
__device__ __forceinline__ uint4 pack8(const float* a) {
    uint4 r;
    __half2 h;
    h = __float22half2_rn(make_float2(a[0], a[1])); r.x = *(uint32_t*)&h;
    h = __float22half2_rn(make_float2(a[2], a[3])); r.y = *(uint32_t*)&h;
    h = __float22half2_rn(make_float2(a[4], a[5])); r.z = *(uint32_t*)&h;
    h = __float22half2_rn(make_float2(a[6], a[7])); r.w = *(uint32_t*)&h;
    return r;
}

// ================= static device scratch =================
__device__ __align__(128) __half g_xf16[NT * NN * HD];
__device__ __align__(128) __half g_hf16[NL][NN * HD];
__device__ __align__(128) __half g_z0[NN * HD];
__device__ __align__(128) __half g_z1[NN * HD];
__device__ __align__(128) __half g_rh0[NN * HD];
__device__ __align__(128) __half g_rh1[NN * HD];
__device__ __align__(128) __half g_aX[NN * HD];
__device__ __align__(128) __half g_aY[NN * HD];
__device__ __align__(128) __half g_aH0[NN * HD];
__device__ int   g_cnt[NN];
__device__ int   g_cur[NN];
__device__ int   g_offs[NN + 1];
__device__ float g_dinv[NN];
__device__ int2  g_epack[NE];
__device__ int   g_bsum[64];
__device__ int   g_bbase[64];
__device__ __align__(128) __half g_Bzr[NL * 256 * 256];
__device__ __align__(128) __half g_Bh [NL * 128 * 256];
__device__ float g_bzr[NL][256];
__device__ float g_bh [NL][128];

// ================= setup kernels =================
__global__ void k_zero() {
    int i = blockIdx.x * blockDim.x + threadIdx.x;
    if (i < NN) { g_cnt[i] = 0; g_cur[i] = 0; }
}
__global__ void k_count(const int* __restrict__ ei) {
    int e = blockIdx.x * blockDim.x + threadIdx.x;
    if (e < NE) atomicAdd(&g_cnt[ei[e]], 1);
}
__global__ void k_scan1() {
    __shared__ int s[1024];
    int t = threadIdx.x;
    int i = blockIdx.x * 1024 + t;
    int v = (i < NN) ? g_cnt[i] : 0;
    if (i < NN) g_dinv[i] = rsqrtf((float)(v + 2));
    s[t] = v; __syncthreads();
    #pragma unroll
    for (int off = 1; off < 1024; off <<= 1) {
        int x = (t >= off) ? s[t - off] : 0;
        __syncthreads(); s[t] += x; __syncthreads();
    }
    if (i < NN) g_offs[i] = s[t] - v;
    if (t == 1023) g_bsum[blockIdx.x] = s[1023];
}
__global__ void k_scan2() {
    __shared__ int s[64];
    int t = threadIdx.x;
    const int NB = (NN + 1023) / 1024;
    int v = (t < NB) ? g_bsum[t] : 0;
    s[t] = v; __syncthreads();
    #pragma unroll
    for (int off = 1; off < 64; off <<= 1) {
        int x = (t >= off) ? s[t - off] : 0;
        __syncthreads(); s[t] += x; __syncthreads();
    }
    if (t < NB) g_bbase[t] = s[t] - v;
    if (t == 63) g_offs[NN] = s[63];
}
__global__ void k_scan3() {
    int i = blockIdx.x * 1024 + threadIdx.x;
    if (i < NN) g_offs[i] += g_bbase[blockIdx.x];
}
__global__ void k_fill(const int* __restrict__ ei) {
    int e = blockIdx.x * blockDim.x + threadIdx.x;
    if (e < NE) {
        int r = ei[e];
        int c = ei[NE + e];
        int pos = g_offs[r] + atomicAdd(&g_cur[r], 1);
        g_epack[pos] = make_int2(c, __float_as_int(g_dinv[r] * g_dinv[c]));
    }
}
__global__ void k_init(const float* __restrict__ Wxz, const float* __restrict__ Whz,
                       const float* __restrict__ Wxr, const float* __restrict__ Whr,
                       const float* __restrict__ Wxh, const float* __restrict__ Whh,
                       const float* __restrict__ bxz, const float* __restrict__ bhz,
                       const float* __restrict__ bxr, const float* __restrict__ bhr,
                       const float* __restrict__ bxh, const float* __restrict__ bhh,
                       const float4* __restrict__ h0, const float4* __restrict__ x) {
    int i = blockIdx.x * blockDim.x + threadIdx.x;
    const int ZR = NL * 256 * 256;
    const int HS = NL * 128 * 256;
    const int B1 = ZR + HS;
    const int B2 = B1 + NL * 256;
    const int B3 = B2 + NL * 128;
    const int CP = NL * NN * HD / 4;
    const int B4 = B3 + CP;
    const int XC = NT * NN * HD / 4;
    if (i < ZR) {
        int l = i / (256 * 256);
        int nk = i % (256 * 256);
        int n = nk / 256, k = nk % 256;
        const float* W = (k < 128) ? ((n < 128) ? Wxz : Wxr)
                                   : ((n < 128) ? Whz : Whr);
        g_Bzr[l * 256 * 256 + nk] =
            __float2half_rn(W[l * HD * HD + (k & 127) * HD + (n & 127)]);
    } else if (i < B1) {
        int i2 = i - ZR;
        int l = i2 / (128 * 256);
        int nk = i2 % (128 * 256);
        int n = nk / 256, k = nk % 256;
        const float* W = (k < 128) ? Wxh : Whh;
        g_Bh[l * 128 * 256 + nk] =
            __float2half_rn(W[l * HD * HD + (k & 127) * HD + n]);
    } else if (i < B2) {
        int i2 = i - B1;
        int l = i2 / 256, j = i2 % 256;
        g_bzr[l][j] = (j < 128) ? (bxz[l * HD + j] + bhz[l * HD + j])
                                : (bxr[l * HD + j - 128] + bhr[l * HD + j - 128]);
    } else if (i < B3) {
        int i2 = i - B2;
        int l = i2 / 128, j = i2 % 128;
        g_bh[l][j] = bxh[l * HD + j] + bhh[l * HD + j];
    } else if (i < B4) {
        int j = i - B3;
        ((uint2*)&g_hf16[0][0])[j] = packh4(h0[j]);
    } else if (i - B4 < XC) {
        int j = i - B4;
        ((uint2*)&g_xf16[0])[j] = packh4(x[j]);
    }
}

// ================= SpMM kernels =================
__global__ void __launch_bounds__(256) k_spmm2(
    const __half* __restrict__ srcA, const __half* __restrict__ srcB,
    __half* __restrict__ oA, __half* __restrict__ oB) {
    int row = (blockIdx.x * blockDim.x + threadIdx.x) >> 5;
    int lane = threadIdx.x & 31;
    if (row >= NN) return;
    int hw = lane >> 4, sl = lane & 15;
    const uint4* sA = (const uint4*)srcA;
    const uint4* sB = (const uint4*)srcB;
    float aA[8], aB[8];
    #pragma unroll
    for (int k = 0; k < 8; ++k) { aA[k] = 0.f; aB[k] = 0.f; }
    int e0 = g_offs[row], end = g_offs[row + 1];
    #pragma unroll 4
    for (int e = e0 + hw; e < end; e += 2) {
        int2 ew = g_epack[e];
        float w = __int_as_float(ew.y);
        acc8(aA, sA[(size_t)ew.x * 16 + sl], w);
        acc8(aB, sB[(size_t)ew.x * 16 + sl], w);
    }
    #pragma unroll
    for (int k = 0; k < 8; ++k) {
        aA[k] += __shfl_xor_sync(0xffffffff, aA[k], 16);
        aB[k] += __shfl_xor_sync(0xffffffff, aB[k], 16);
    }
    if (hw == 0) {
        float di = g_dinv[row];
        float ws = 2.f * di * di;
        acc8(aA, sA[(size_t)row * 16 + sl], ws);
        acc8(aB, sB[(size_t)row * 16 + sl], ws);
        ((uint4*)oA)[(size_t)row * 16 + sl] = pack8(aA);
        ((uint4*)oB)[(size_t)row * 16 + sl] = pack8(aB);
    }
}

// triple gather (h0, h1, x_{t+1}) in one edge pass
__global__ void __launch_bounds__(256) k_spmm3(
    const __half* __restrict__ srcA, const __half* __restrict__ srcB,
    const __half* __restrict__ srcC,
    __half* __restrict__ oA, __half* __restrict__ oB, __half* __restrict__ oC) {
    int row = (blockIdx.x * blockDim.x + threadIdx.x) >> 5;
    int lane = threadIdx.x & 31;
    if (row >= NN) return;
    int hw = lane >> 4, sl = lane & 15;
    const uint4* sA = (const uint4*)srcA;
    const uint4* sB = (const uint4*)srcB;
    const uint4* sC = (const uint4*)srcC;
    float aA[8], aB[8], aC[8];
    #pragma unroll
    for (int k = 0; k < 8; ++k) { aA[k] = 0.f; aB[k] = 0.f; aC[k] = 0.f; }
    int e0 = g_offs[row], end = g_offs[row + 1];
    #pragma unroll 2
    for (int e = e0 + hw; e < end; e += 2) {
        int2 ew = g_epack[e];
        float w = __int_as_float(ew.y);
        acc8(aA, sA[(size_t)ew.x * 16 + sl], w);
        acc8(aB, sB[(size_t)ew.x * 16 + sl], w);
        acc8(aC, sC[(size_t)ew.x * 16 + sl], w);
    }
    #pragma unroll
    for (int k = 0; k < 8; ++k) {
        aA[k] += __shfl_xor_sync(0xffffffff, aA[k], 16);
        aB[k] += __shfl_xor_sync(0xffffffff, aB[k], 16);
        aC[k] += __shfl_xor_sync(0xffffffff, aC[k], 16);
    }
    if (hw == 0) {
        float di = g_dinv[row];
        float ws = 2.f * di * di;
        acc8(aA, sA[(size_t)row * 16 + sl], ws);
        acc8(aB, sB[(size_t)row * 16 + sl], ws);
        acc8(aC, sC[(size_t)row * 16 + sl], ws);
        ((uint4*)oA)[(size_t)row * 16 + sl] = pack8(aA);
        ((uint4*)oB)[(size_t)row * 16 + sl] = pack8(aB);
        ((uint4*)oC)[(size_t)row * 16 + sl] = pack8(aC);
    }
}

// ================= gemm0 (MODE0): NCOL=64 tiles, 4x2 warp grid (R10 proven) ========
// nBase=0: z = sigmoid(v); nBase=128: rh = sigmoid(v)*h
#define STAGE_SZ 24576
#define SMEM_G0 (2 * STAGE_SZ)

__global__ void __launch_bounds__(256) k_gemm0(
    const __half* __restrict__ Ax, const __half* __restrict__ Ay,
    const __half* __restrict__ B, const float* __restrict__ bias,
    const __half* __restrict__ hP, __half* __restrict__ outP, int nBase) {

    extern __shared__ char smem[];
    uint32_t sb = smem_u32(smem);
    int tid = threadIdx.x;
    int lane = tid & 31, warp = tid >> 5;
    int wm = warp >> 1, wn = warp & 1;
    int rowBase = blockIdx.x * 128;
    int nTile = nBase + blockIdx.y * 64;

    float acc[2][4][4];
    #pragma unroll
    for (int i = 0; i < 2; ++i)
        #pragma unroll
        for (int j = 0; j < 4; ++j)
            #pragma unroll
            for (int q = 0; q < 4; ++q) acc[i][j][q] = 0.f;

    const uint32_t swx = (uint32_t)(lane & 7) << 4;

    auto prefetch = [&](int s, int b) {
        const __half* Ap = (s < 2) ? Ax : Ay;
        int ka = (s & 1) * 64;
        int kb = s * 64;
        uint32_t base = sb + (uint32_t)b * STAGE_SZ;
        #pragma unroll
        for (int u = 0; u < 4; ++u) {
            int idx = u * 256 + tid;
            int row = idx >> 3, c = idx & 7;
            uint32_t soff = (uint32_t)row * 128 +
                            (((uint32_t)c * 16) ^ (((uint32_t)row & 7) << 4));
            int gm = rowBase + row;
            cpa16(base + soff, Ap + (size_t)gm * HD + ka + c * 8, gm < NN);
        }
        #pragma unroll
        for (int u = 0; u < 2; ++u) {
            int idx = u * 256 + tid;
            int row = idx >> 3, c = idx & 7;
            uint32_t soff = (uint32_t)row * 128 +
                            (((uint32_t)c * 16) ^ (((uint32_t)row & 7) << 4));
            int gn = nTile + row;
            cpa16(base + 16384 + soff, B + (size_t)gn * 256 + kb + c * 8, true);
        }
    };

    prefetch(0, 0); CP_COMMIT();
    prefetch(1, 1); CP_COMMIT();

    #pragma unroll 1
    for (int s = 0; s < 4; ++s) {
        CP_WAIT1();
        __syncthreads();
        uint32_t aBase = sb + (uint32_t)(s & 1) * STAGE_SZ;
        #pragma unroll
        for (int kk = 0; kk < 4; ++kk) {
            uint32_t a[2][4], bf[4][2];
            #pragma unroll
            for (int i = 0; i < 2; ++i) {
                uint32_t m = (uint32_t)(wm * 32 + i * 16 + (lane & 15));
                uint32_t k2 = (uint32_t)(kk * 16 + ((lane & 16) >> 1)) * 2;
                ldsm4(a[i], aBase + m * 128 + (k2 ^ swx));
            }
            #pragma unroll
            for (int jj = 0; jj < 2; ++jj) {
                uint32_t n = (uint32_t)(wn * 32 + jj * 16 + (lane & 7) + ((lane & 16) >> 1));
                uint32_t k2 = (uint32_t)(kk * 16 + (lane & 8)) * 2;
                uint32_t r[4];
                ldsm4(r, aBase + 16384 + n * 128 + (k2 ^ swx));
                bf[jj * 2][0] = r[0]; bf[jj * 2][1] = r[1];
                bf[jj * 2 + 1][0] = r[2]; bf[jj * 2 + 1][1] = r[3];
            }
            #pragma unroll
            for (int i = 0; i < 2; ++i)
                #pragma unroll
                for (int j = 0; j < 4; ++j)
                    mma16816(acc[i][j], a[i], bf[j]);
        }
        __syncthreads();
        if (s < 2) prefetch(s + 2, s & 1);
        CP_COMMIT();
    }

    #pragma unroll
    for (int j = 0; j < 4; ++j) {
        int cl = wn * 32 + j * 8 + (lane & 3) * 2;
        int c0 = nTile + cl;
        float bs0 = bias[c0], bs1 = bias[c0 + 1];
        #pragma unroll
        for (int i = 0; i < 2; ++i) {
            #pragma unroll
            for (int half = 0; half < 2; ++half) {
                int m0 = rowBase + wm * 32 + i * 16 + (lane >> 2) + half * 8;
                if (m0 >= NN) continue;
                float v0 = sigf(acc[i][j][half * 2 + 0] + bs0);
                float v1 = sigf(acc[i][j][half * 2 + 1] + bs1);
                if (c0 < 128) {
                    *(__half2*)(outP + (size_t)m0 * HD + c0) =
                        __float22half2_rn(make_float2(v0, v1));
                } else {
                    int n2 = c0 - 128;
                    float2 hv = __half22float2(*(__half2*)(hP + (size_t)m0 * HD + n2));
                    *(__half2*)(outP + (size_t)m0 * HD + n2) =
                        __float22half2_rn(make_float2(v0 * hv.x, v1 * hv.y));
                }
            }
        }
    }
}

// ================= fused gemm1: in-block rh-gather + GEMM + GRU epilogue ========
// C[M=128, N=128] over K=256: stages 0,1 A=Ax (cp.async), stages 2,3 A=A@rh
// gathered in-block into smem. 8 warps 2x4 grid (64x32 warp tiles).
// smem: pipe 2 x (A 16KB + B 16KB) = 64KB @0; gathered aR 2 x 16KB @65536. 96KB.
#define SMEM_G1 98304

__global__ void __launch_bounds__(256) k_gemm1f(
    const __half* __restrict__ Ax, const __half* __restrict__ rhSrc,
    const __half* __restrict__ B, const float* __restrict__ bias,
    __half* __restrict__ hP, const __half* __restrict__ zP,
    float* __restrict__ outF) {

    extern __shared__ char smem[];
    uint32_t sb = smem_u32(smem);
    int tid = threadIdx.x;
    int lane = tid & 31, warp = tid >> 5;
    int wm = warp >> 2, wn = warp & 3;      // 2x4; warp tile 64x32
    int rowBase = blockIdx.x * 128;

    const uint32_t swx = (uint32_t)(lane & 7) << 4;

    auto prefetch = [&](int s, int b) {
        uint32_t base = sb + (uint32_t)b * 32768;
        if (s < 2) {
            int ka = s * 64;
            #pragma unroll
            for (int u = 0; u < 4; ++u) {
                int idx = u * 256 + tid;
                int row = idx >> 3, c = idx & 7;
                uint32_t soff = (uint32_t)row * 128 +
                                (((uint32_t)c * 16) ^ (((uint32_t)row & 7) << 4));
                int gm = rowBase + row;
                cpa16(base + soff, Ax + (size_t)gm * HD + ka + c * 8, gm < NN);
            }
        }
        int kb = s * 64;
        #pragma unroll
        for (int u = 0; u < 4; ++u) {
            int idx = u * 256 + tid;
            int row = idx >> 3, c = idx & 7;
            uint32_t soff = (uint32_t)row * 128 +
                            (((uint32_t)c * 16) ^ (((uint32_t)row & 7) << 4));
            cpa16(base + 16384 + soff, B + (size_t)row * 256 + kb + c * 8, true);
        }
    };

    prefetch(0, 0); CP_COMMIT();
    prefetch(1, 1); CP_COMMIT();

    // ---- in-block gather: aR[rowBase..rowBase+127] = (A @ rh)[rows] -> smem ----
    {
        int hw = lane >> 4, sl = lane & 15;
        const uint4* s4 = (const uint4*)rhSrc;
        #pragma unroll 1
        for (int r = 0; r < 16; ++r) {
            int row = warp * 16 + r;
            int gm = rowBase + row;
            float a[8];
            #pragma unroll
            for (int k = 0; k < 8; ++k) a[k] = 0.f;
            if (gm < NN) {
                int e0 = g_offs[gm], end = g_offs[gm + 1];
                #pragma unroll 4
                for (int e = e0 + hw; e < end; e += 2) {
                    int2 ew = g_epack[e];
                    acc8(a, s4[(size_t)ew.x * 16 + sl], __int_as_float(ew.y));
                }
            }
            #pragma unroll
            for (int k = 0; k < 8; ++k)
                a[k] += __shfl_xor_sync(0xffffffff, a[k], 16);
            if (hw == 0) {
                if (gm < NN) {
                    float di = g_dinv[gm];
                    acc8(a, s4[(size_t)gm * 16 + sl], 2.f * di * di);
                }
                uint32_t soff = (uint32_t)row * 128 +
                                (((uint32_t)(sl & 7) * 16) ^ (((uint32_t)row & 7) << 4));
                *(uint4*)(smem + 65536 + (sl >> 3) * 16384 + soff) = pack8(a);
            }
        }
    }

    float acc[4][4][4];
    #pragma unroll
    for (int i = 0; i < 4; ++i)
        #pragma unroll
        for (int j = 0; j < 4; ++j)
            #pragma unroll
            for (int q = 0; q < 4; ++q) acc[i][j][q] = 0.f;

    #pragma unroll 1
    for (int s = 0; s < 4; ++s) {
        CP_WAIT1();
        __syncthreads();
        uint32_t aBase = (s < 2) ? sb + (uint32_t)(s & 1) * 32768
                                 : sb + 65536 + (uint32_t)(s - 2) * 16384;
        uint32_t bBase = sb + (uint32_t)(s & 1) * 32768 + 16384;
        #pragma unroll
        for (int kk = 0; kk < 4; ++kk) {
            uint32_t a[4][4], bf[4][2];
            #pragma unroll
            for (int i = 0; i < 4; ++i) {
                uint32_t m = (uint32_t)(wm * 64 + i * 16 + (lane & 15));
                uint32_t k2 = (uint32_t)(kk * 16 + ((lane & 16) >> 1)) * 2;
                ldsm4(a[i], aBase + m * 128 + (k2 ^ swx));
            }
            #pragma unroll
            for (int jj = 0; jj < 2; ++jj) {
                uint32_t n = (uint32_t)(wn * 32 + jj * 16 + (lane & 7) + ((lane & 16) >> 1));
                uint32_t k2 = (uint32_t)(kk * 16 + (lane & 8)) * 2;
                uint32_t r[4];
                ldsm4(r, bBase + n * 128 + (k2 ^ swx));
                bf[jj * 2][0] = r[0]; bf[jj * 2][1] = r[1];
                bf[jj * 2 + 1][0] = r[2]; bf[jj * 2 + 1][1] = r[3];
            }
            #pragma unroll
            for (int i = 0; i < 4; ++i)
                #pragma unroll
                for (int j = 0; j < 4; ++j)
                    mma16816(acc[i][j], a[i], bf[j]);
        }
        __syncthreads();
        if (s < 2) prefetch(s + 2, s & 1);
        CP_COMMIT();
    }

    // ---- GRU epilogue: hn = z*h + (1-z)*tanh(v) ----
    #pragma unroll
    for (int j = 0; j < 4; ++j) {
        int c0 = wn * 32 + j * 8 + (lane & 3) * 2;
        float bs0 = bias[c0], bs1 = bias[c0 + 1];
        #pragma unroll
        for (int i = 0; i < 4; ++i) {
            #pragma unroll
            for (int half = 0; half < 2; ++half) {
                int m0 = rowBase + wm * 64 + i * 16 + (lane >> 2) + half * 8;
                if (m0 >= NN) continue;
                float v0 = acc[i][j][half * 2 + 0] + bs0;
                float v1 = acc[i][j][half * 2 + 1] + bs1;
                float2 hv = __half22float2(*(__half2*)(hP + (size_t)m0 * HD + c0));
                float2 zv = __half22float2(*(__half2*)(zP + (size_t)m0 * HD + c0));
                float o0 = zv.x * hv.x + (1.f - zv.x) * tanhf(v0);
                float o1 = zv.y * hv.y + (1.f - zv.y) * tanhf(v1);
                *(__half2*)(hP + (size_t)m0 * HD + c0) =
                    __float22half2_rn(make_float2(o0, o1));
                if (outF)
                    *(float2*)(outF + (size_t)m0 * HD + c0) = make_float2(o0, o1);
            }
        }
    }
}

// ================= host =================
extern "C" void kernel_launch(void* const* d_in, const int* in_sizes, int n_in,
                              void* d_out, int out_size) {
    if (n_in < 15) return;
    const float* x   = (const float*)d_in[0];
    const float* h0  = (const float*)d_in[1];
    const int*   ei  = (const int*)  d_in[2];
    const float* Wxz = (const float*)d_in[3];
    const float* Whz = (const float*)d_in[4];
    const float* Wxr = (const float*)d_in[5];
    const float* Whr = (const float*)d_in[6];
    const float* Wxh = (const float*)d_in[7];
    const float* Whh = (const float*)d_in[8];
    const float* bxz = (const float*)d_in[9];
    const float* bhz = (const float*)d_in[10];
    const float* bxr = (const float*)d_in[11];
    const float* bhr = (const float*)d_in[12];
    const float* bxh = (const float*)d_in[13];
    const float* bhh = (const float*)d_in[14];
    float* out = (float*)d_out;

    float *p_bzr, *p_bh;
    __half *p_xf16, *p_hf16, *p_z0, *p_z1, *p_rh0, *p_rh1;
    __half *p_aX, *p_aY, *p_aH0, *p_Bzr, *p_Bh;
    cudaGetSymbolAddress((void**)&p_xf16, g_xf16);
    cudaGetSymbolAddress((void**)&p_hf16, g_hf16);
    cudaGetSymbolAddress((void**)&p_z0,   g_z0);
    cudaGetSymbolAddress((void**)&p_z1,   g_z1);
    cudaGetSymbolAddress((void**)&p_rh0,  g_rh0);
    cudaGetSymbolAddress((void**)&p_rh1,  g_rh1);
    cudaGetSymbolAddress((void**)&p_aX,   g_aX);
    cudaGetSymbolAddress((void**)&p_aY,   g_aY);
    cudaGetSymbolAddress((void**)&p_aH0,  g_aH0);
    cudaGetSymbolAddress((void**)&p_Bzr,  g_Bzr);
    cudaGetSymbolAddress((void**)&p_Bh,   g_Bh);
    cudaGetSymbolAddress((void**)&p_bzr,  g_bzr);
    cudaGetSymbolAddress((void**)&p_bh,   g_bh);

    cudaFuncSetAttribute((const void*)k_gemm0,
                         cudaFuncAttributeMaxDynamicSharedMemorySize, SMEM_G0);
    cudaFuncSetAttribute((const void*)k_gemm1f,
                         cudaFuncAttributeMaxDynamicSharedMemorySize, SMEM_G1);

    static cudaStream_t s2 = nullptr;
    static cudaEvent_t evS = nullptr, evI = nullptr, e1 = nullptr, e2 = nullptr,
                       e3 = nullptr, e4 = nullptr, evG = nullptr;
    if (!s2) {
        cudaStreamCreateWithFlags(&s2, cudaStreamNonBlocking);
        cudaEventCreateWithFlags(&evS, cudaEventDisableTiming);
        cudaEventCreateWithFlags(&evI, cudaEventDisableTiming);
        cudaEventCreateWithFlags(&e1,  cudaEventDisableTiming);
        cudaEventCreateWithFlags(&e2,  cudaEventDisableTiming);
        cudaEventCreateWithFlags(&e3,  cudaEventDisableTiming);
        cudaEventCreateWithFlags(&e4,  cudaEventDisableTiming);
        cudaEventCreateWithFlags(&evG, cudaEventDisableTiming);
    }

    const int NB = (NN + 1023) / 1024;
    const int spmm_blocks = (NN + 7) / 8;
    const int gM = (NN + 127) / 128;  // 391

    // ---- setup: fork k_init onto s2, CSR build on main ----
    k_zero<<<(NN + 255) / 256, 256>>>();
    cudaEventRecord(evS, 0);
    cudaStreamWaitEvent(s2, evS, 0);
    {
        int tot = NL * 256 * 256 + NL * 128 * 256 + NL * 256 + NL * 128
                + NL * NN * HD / 4 + NT * NN * HD / 4;
        k_init<<<(tot + 255) / 256, 256, 0, s2>>>(Wxz, Whz, Wxr, Whr, Wxh, Whh,
                                                  bxz, bhz, bxr, bhr, bxh, bhh,
                                                  (const float4*)h0, (const float4*)x);
    }
    cudaEventRecord(evI, s2);
    k_count<<<(NE + 255) / 256, 256>>>(ei);
    k_scan1<<<NB, 1024>>>();
    k_scan2<<<1, 64>>>();
    k_scan3<<<NB, 1024>>>();
    k_fill<<<(NE + 255) / 256, 256>>>(ei);
    cudaStreamWaitEvent(0, evI, 0);

    __half* h0_16 = p_hf16;
    __half* h1_16 = p_hf16 + (size_t)NN * HD;

    // prologue: aX = A@x_0, aH0 = A@h0_init
    k_spmm2<<<spmm_blocks, 256>>>(p_xf16, h0_16, p_aX, p_aH0);

    for (int t = 0; t < NT; ++t) {
        // fork A_z on s2 concurrent with A_rh on main (inputs ready on main now)
        cudaEventRecord(e1, 0);
        cudaStreamWaitEvent(s2, e1, 0);
        k_gemm0<<<dim3(gM, 2), 256, SMEM_G0, s2>>>(
            p_aX, p_aH0, p_Bzr, p_bzr, h0_16, p_z0, 0);           // A_z -> z0
        cudaEventRecord(e2, s2);
        k_gemm0<<<dim3(gM, 2), 256, SMEM_G0>>>(
            p_aX, p_aH0, p_Bzr, p_bzr, h0_16, p_rh0, 128);        // A_rh -> rh0
        cudaStreamWaitEvent(0, e2, 0);
        // C': fused gather(rh0) + gemm1 L0 -> h0
        k_gemm1f<<<gM, 256, SMEM_G1>>>(
            p_aX, p_rh0, p_Bh, p_bh, h0_16, p_z0, nullptr);
        // D: triple gather (waits G'(t-1): reads h1, writes aH0 G' reads)
        if (t > 0) cudaStreamWaitEvent(0, evG, 0);
        if (t + 1 < NT) {
            k_spmm3<<<spmm_blocks, 256>>>(h0_16, h1_16,
                                          p_xf16 + (size_t)(t + 1) * NN * HD,
                                          p_aH0, p_aY, p_aX);
        } else {
            k_spmm2<<<spmm_blocks, 256>>>(h0_16, h1_16, p_aH0, p_aY);
        }
        // fork E_z on s2 concurrent with E_rh on main
        cudaEventRecord(e3, 0);
        cudaStreamWaitEvent(s2, e3, 0);
        k_gemm0<<<dim3(gM, 2), 256, SMEM_G0, s2>>>(
            p_aH0, p_aY, p_Bzr + 256 * 256, p_bzr + 256, h1_16, p_z1, 0);   // E_z
        k_gemm0<<<dim3(gM, 2), 256, SMEM_G0>>>(
            p_aH0, p_aY, p_Bzr + 256 * 256, p_bzr + 256, h1_16, p_rh1, 128); // E_rh
        cudaEventRecord(e4, 0);
        // G': fused gather(rh1) + gemm1 L1 -> h1, out  (s2; overlaps next A-phase)
        cudaStreamWaitEvent(s2, e4, 0);
        k_gemm1f<<<gM, 256, SMEM_G1, s2>>>(
            p_aH0, p_rh1, p_Bh + 128 * 256, p_bh + 128,
            h1_16, p_z1, out + (size_t)t * NN * HD);
        cudaEventRecord(evG, s2);
    }
    cudaStreamWaitEvent(0, evG, 0);
}

// round 15
// speedup vs baseline: 1.4105x; 1.4105x over previous
#include <cuda_runtime.h>
#include <cuda_fp16.h>
#include <math.h>
#include <stdint.h>

#define NT 8
#define NN 50000
#define NE 800000
#define HD 128
#define NL 2

__device__ __forceinline__ uint32_t smem_u32(const void* p) {
    uint32_t a;
    asm("{ .reg .u64 t; cvta.to.shared.u64 t, %1; cvt.u32.u64 %0, t; }" : "=r"(a) : "l"(p));
    return a;
}
__device__ __forceinline__ float sigf(float x) { return 1.f / (1.f + __expf(-x)); }

__device__ __forceinline__ void mma16816(float* d, const uint32_t* a, const uint32_t* b) {
    asm volatile("mma.sync.aligned.m16n8k16.row.col.f32.f16.f16.f32 "
        "{%0,%1,%2,%3}, {%4,%5,%6,%7}, {%8,%9}, {%0,%1,%2,%3};"
        : "+f"(d[0]), "+f"(d[1]), "+f"(d[2]), "+f"(d[3])
        : "r"(a[0]), "r"(a[1]), "r"(a[2]), "r"(a[3]), "r"(b[0]), "r"(b[1]));
}
__device__ __forceinline__ void ldsm4(uint32_t* r, uint32_t addr) {
    asm volatile("ldmatrix.sync.aligned.m8n8.x4.shared.b16 {%0,%1,%2,%3}, [%4];"
        : "=r"(r[0]), "=r"(r[1]), "=r"(r[2]), "=r"(r[3]) : "r"(addr));
}
__device__ __forceinline__ void cpa16(uint32_t dst, const void* src, bool pred) {
    asm volatile("cp.async.cg.shared.global [%0], [%1], 16, %2;"
        :: "r"(dst), "l"(__cvta_generic_to_global(src)), "r"(pred ? 16 : 0) : "memory");
}
#define CP_COMMIT() asm volatile("cp.async.commit_group;" ::: "memory")
#define CP_WAIT1()  asm volatile("cp.async.wait_group 1;" ::: "memory")

__device__ __forceinline__ uint2 packh4(float4 a) {
    __half2 p0 = __float22half2_rn(make_float2(a.x, a.y));
    __half2 p1 = __float22half2_rn(make_float2(a.z, a.w));
    uint2 r;
    r.x = *(uint32_t*)&p0;
    r.y = *(uint32_t*)&p1;
    return r;
}
__device__ __forceinline__ void acc8(float* a, uint4 u, float w) {
    float2 f;
    f = __half22float2(*(__half2*)&u.x); a[0] += w * f.x; a[1] += w * f.y;
    f = __half22float2(*(__half2*)&u.y); a[2] += w * f.x; a[3] += w * f.y;
    f = __half22float2(*(__half2*)&u.z); a[4] += w * f.x; a[5] += w * f.y;
    f = __half22float2(*(__half2*)&u.w); a[6] += w * f.x; a[7] += w * f.y;
}
__device__ __forceinline__ uint4 pack8(const float* a) {
    uint4 r;
    __half2 h;
    h = __float22half2_rn(make_float2(a[0], a[1])); r.x = *(uint32_t*)&h;
    h = __float22half2_rn(make_float2(a[2], a[3])); r.y = *(uint32_t*)&h;
    h = __float22half2_rn(make_float2(a[4], a[5])); r.z = *(uint32_t*)&h;
    h = __float22half2_rn(make_float2(a[6], a[7])); r.w = *(uint32_t*)&h;
    return r;
}

// ================= static device scratch =================
__device__ __align__(128) __half g_xf16[NT * NN * HD];
__device__ __align__(128) __half g_hf16[NL][NN * HD];
__device__ __align__(128) __half g_z0[NN * HD];
__device__ __align__(128) __half g_z1[NN * HD];
__device__ __align__(128) __half g_rhf16[NN * HD];
__device__ __align__(128) __half g_aX[NN * HD];
__device__ __align__(128) __half g_aY[NN * HD];
__device__ __align__(128) __half g_aH0[NN * HD];
__device__ __align__(128) __half g_aR[NN * HD];
__device__ int   g_cnt[NN];
__device__ int   g_cur[NN];
__device__ int   g_offs[NN + 1];
__device__ float g_dinv[NN];
__device__ int2  g_epack[NE];
__device__ int   g_bsum[64];
__device__ int   g_bbase[64];
__device__ __align__(128) __half g_Bzr[NL * 256 * 256];
__device__ __align__(128) __half g_Bh [NL * 128 * 256];
__device__ float g_bzr[NL][256];
__device__ float g_bh [NL][128];

// ================= setup kernels =================
__global__ void k_zero() {
    int i = blockIdx.x * blockDim.x + threadIdx.x;
    if (i < NN) { g_cnt[i] = 0; g_cur[i] = 0; }
}
__global__ void k_count(const int* __restrict__ ei) {
    int e = blockIdx.x * blockDim.x + threadIdx.x;
    if (e < NE) atomicAdd(&g_cnt[ei[e]], 1);
}
__global__ void k_scan1() {
    __shared__ int s[1024];
    int t = threadIdx.x;
    int i = blockIdx.x * 1024 + t;
    int v = (i < NN) ? g_cnt[i] : 0;
    if (i < NN) g_dinv[i] = rsqrtf((float)(v + 2));
    s[t] = v; __syncthreads();
    #pragma unroll
    for (int off = 1; off < 1024; off <<= 1) {
        int x = (t >= off) ? s[t - off] : 0;
        __syncthreads(); s[t] += x; __syncthreads();
    }
    if (i < NN) g_offs[i] = s[t] - v;
    if (t == 1023) g_bsum[blockIdx.x] = s[1023];
}
__global__ void k_scan2() {
    __shared__ int s[64];
    int t = threadIdx.x;
    const int NB = (NN + 1023) / 1024;
    int v = (t < NB) ? g_bsum[t] : 0;
    s[t] = v; __syncthreads();
    #pragma unroll
    for (int off = 1; off < 64; off <<= 1) {
        int x = (t >= off) ? s[t - off] : 0;
        __syncthreads(); s[t] += x; __syncthreads();
    }
    if (t < NB) g_bbase[t] = s[t] - v;
    if (t == 63) g_offs[NN] = s[63];
}
__global__ void k_scan3() {
    int i = blockIdx.x * 1024 + threadIdx.x;
    if (i < NN) g_offs[i] += g_bbase[blockIdx.x];
}
__global__ void k_fill(const int* __restrict__ ei) {
    int e = blockIdx.x * blockDim.x + threadIdx.x;
    if (e < NE) {
        int r = ei[e];
        int c = ei[NE + e];
        int pos = g_offs[r] + atomicAdd(&g_cur[r], 1);
        g_epack[pos] = make_int2(c, __float_as_int(g_dinv[r] * g_dinv[c]));
    }
}
__global__ void k_init(const float* __restrict__ Wxz, const float* __restrict__ Whz,
                       const float* __restrict__ Wxr, const float* __restrict__ Whr,
                       const float* __restrict__ Wxh, const float* __restrict__ Whh,
                       const float* __restrict__ bxz, const float* __restrict__ bhz,
                       const float* __restrict__ bxr, const float* __restrict__ bhr,
                       const float* __restrict__ bxh, const float* __restrict__ bhh,
                       const float4* __restrict__ h0, const float4* __restrict__ x) {
    int i = blockIdx.x * blockDim.x + threadIdx.x;
    const int ZR = NL * 256 * 256;
    const int HS = NL * 128 * 256;
    const int B1 = ZR + HS;
    const int B2 = B1 + NL * 256;
    const int B3 = B2 + NL * 128;
    const int CP = NL * NN * HD / 4;
    const int B4 = B3 + CP;
    const int XC = NT * NN * HD / 4;
    if (i < ZR) {
        int l = i / (256 * 256);
        int nk = i % (256 * 256);
        int n = nk / 256, k = nk % 256;
        const float* W = (k < 128) ? ((n < 128) ? Wxz : Wxr)
                                   : ((n < 128) ? Whz : Whr);
        g_Bzr[l * 256 * 256 + nk] =
            __float2half_rn(W[l * HD * HD + (k & 127) * HD + (n & 127)]);
    } else if (i < B1) {
        int i2 = i - ZR;
        int l = i2 / (128 * 256);
        int nk = i2 % (128 * 256);
        int n = nk / 256, k = nk % 256;
        const float* W = (k < 128) ? Wxh : Whh;
        g_Bh[l * 128 * 256 + nk] =
            __float2half_rn(W[l * HD * HD + (k & 127) * HD + n]);
    } else if (i < B2) {
        int i2 = i - B1;
        int l = i2 / 256, j = i2 % 256;
        g_bzr[l][j] = (j < 128) ? (bxz[l * HD + j] + bhz[l * HD + j])
                                : (bxr[l * HD + j - 128] + bhr[l * HD + j - 128]);
    } else if (i < B3) {
        int i2 = i - B2;
        int l = i2 / 128, j = i2 % 128;
        g_bh[l][j] = bxh[l * HD + j] + bhh[l * HD + j];
    } else if (i < B4) {
        int j = i - B3;
        ((uint2*)&g_hf16[0][0])[j] = packh4(h0[j]);
    } else if (i - B4 < XC) {
        int j = i - B4;
        ((uint2*)&g_xf16[0])[j] = packh4(x[j]);
    }
}

// ================= SpMM: dual (half-warp per edge, proven) =================
__global__ void __launch_bounds__(256) k_spmm2(
    const __half* __restrict__ srcA, const __half* __restrict__ srcB,
    __half* __restrict__ oA, __half* __restrict__ oB) {
    int row = (blockIdx.x * blockDim.x + threadIdx.x) >> 5;
    int lane = threadIdx.x & 31;
    if (row >= NN) return;
    int hw = lane >> 4, sl = lane & 15;
    const uint4* sA = (const uint4*)srcA;
    const uint4* sB = (const uint4*)srcB;
    float aA[8], aB[8];
    #pragma unroll
    for (int k = 0; k < 8; ++k) { aA[k] = 0.f; aB[k] = 0.f; }
    int e0 = g_offs[row], end = g_offs[row + 1];
    #pragma unroll 4
    for (int e = e0 + hw; e < end; e += 2) {
        int2 ew = g_epack[e];
        float w = __int_as_float(ew.y);
        uint4 u = sA[(size_t)ew.x * 16 + sl];
        uint4 v = sB[(size_t)ew.x * 16 + sl];
        acc8(aA, u, w);
        acc8(aB, v, w);
    }
    #pragma unroll
    for (int k = 0; k < 8; ++k) {
        aA[k] += __shfl_xor_sync(0xffffffff, aA[k], 16);
        aB[k] += __shfl_xor_sync(0xffffffff, aB[k], 16);
    }
    if (hw == 0) {
        float di = g_dinv[row];
        float ws = 2.f * di * di;
        acc8(aA, sA[(size_t)row * 16 + sl], ws);
        acc8(aB, sB[(size_t)row * 16 + sl], ws);
        ((uint4*)oA)[(size_t)row * 16 + sl] = pack8(aA);
        ((uint4*)oB)[(size_t)row * 16 + sl] = pack8(aB);
    }
}

// ================= SpMM single: quarter-warp per edge, 4 edges/warp/iter =================
// Each lane covers 32B of the row (2 independent uint4 loads) -> 2x MLP vs half-warp.
__global__ void __launch_bounds__(256) k_spmm(const __half* __restrict__ src,
                                              __half* __restrict__ o) {
    int row = (blockIdx.x * blockDim.x + threadIdx.x) >> 5;
    int lane = threadIdx.x & 31;
    if (row >= NN) return;
    int qw = lane >> 3, sl = lane & 7;
    const uint4* s4 = (const uint4*)src;
    float a[16];
    #pragma unroll
    for (int k = 0; k < 16; ++k) a[k] = 0.f;
    int e0 = g_offs[row], end = g_offs[row + 1];
    #pragma unroll 4
    for (int e = e0 + qw; e < end; e += 4) {
        int2 ew = g_epack[e];
        float w = __int_as_float(ew.y);
        acc8(a,     s4[(size_t)ew.x * 16 + sl * 2],     w);
        acc8(a + 8, s4[(size_t)ew.x * 16 + sl * 2 + 1], w);
    }
    #pragma unroll
    for (int k = 0; k < 16; ++k) {
        a[k] += __shfl_xor_sync(0xffffffff, a[k], 8);
        a[k] += __shfl_xor_sync(0xffffffff, a[k], 16);
    }
    if (qw == 0) {
        float di = g_dinv[row];
        float ws = 2.f * di * di;
        acc8(a,     s4[(size_t)row * 16 + sl * 2],     ws);
        acc8(a + 8, s4[(size_t)row * 16 + sl * 2 + 1], ws);
        ((uint4*)o)[(size_t)row * 16 + sl * 2]     = pack8(a);
        ((uint4*)o)[(size_t)row * 16 + sl * 2 + 1] = pack8(a + 8);
    }
}

// ================= pipelined HMMA GEMM, NCOL=64 tiles, 4x2 warp grid (R10) =========
#define STAGE_SZ 24576
#define SMEM_GEMM (2 * STAGE_SZ)

template <int MODE>
__global__ void __launch_bounds__(256) k_mma_gemm(
    const __half* __restrict__ Ax, const __half* __restrict__ Ay,
    const __half* __restrict__ B, const float* __restrict__ bias,
    __half* __restrict__ hP, __half* __restrict__ zP,
    __half* __restrict__ rhP, float* __restrict__ outF, int nBase) {

    extern __shared__ char smem[];
    uint32_t sb = smem_u32(smem);
    int tid = threadIdx.x;
    int lane = tid & 31, warp = tid >> 5;
    int wm = warp >> 1;
    int wn = warp & 1;
    int rowBase = blockIdx.x * 128;
    int nTile = nBase + blockIdx.y * 64;

    float acc[2][4][4];
    #pragma unroll
    for (int i = 0; i < 2; ++i)
        #pragma unroll
        for (int j = 0; j < 4; ++j)
            #pragma unroll
            for (int q = 0; q < 4; ++q) acc[i][j][q] = 0.f;

    const uint32_t swx = (uint32_t)(lane & 7) << 4;

    auto prefetch = [&](int s, int b) {
        const __half* Ap = (s < 2) ? Ax : Ay;
        int ka = (s & 1) * 64;
        int kb = s * 64;
        uint32_t base = sb + (uint32_t)b * STAGE_SZ;
        #pragma unroll
        for (int u = 0; u < 4; ++u) {
            int idx = u * 256 + tid;
            int row = idx >> 3, c = idx & 7;
            uint32_t soff = (uint32_t)row * 128 +
                            (((uint32_t)c * 16) ^ (((uint32_t)row & 7) << 4));
            int gm = rowBase + row;
            cpa16(base + soff, Ap + (size_t)gm * HD + ka + c * 8, gm < NN);
        }
        #pragma unroll
        for (int u = 0; u < 2; ++u) {
            int idx = u * 256 + tid;
            int row = idx >> 3, c = idx & 7;
            uint32_t soff = (uint32_t)row * 128 +
                            (((uint32_t)c * 16) ^ (((uint32_t)row & 7) << 4));
            int gn = nTile + row;
            cpa16(base + 16384 + soff, B + (size_t)gn * 256 + kb + c * 8, true);
        }
    };

    prefetch(0, 0); CP_COMMIT();
    prefetch(1, 1); CP_COMMIT();

    #pragma unroll 1
    for (int s = 0; s < 4; ++s) {
        CP_WAIT1();
        __syncthreads();
        uint32_t aBase = sb + (uint32_t)(s & 1) * STAGE_SZ;
        #pragma unroll
        for (int kk = 0; kk < 4; ++kk) {
            uint32_t a[2][4], bf[4][2];
            #pragma unroll
            for (int i = 0; i < 2; ++i) {
                uint32_t m = (uint32_t)(wm * 32 + i * 16 + (lane & 15));
                uint32_t k2 = (uint32_t)(kk * 16 + ((lane & 16) >> 1)) * 2;
                ldsm4(a[i], aBase + m * 128 + (k2 ^ swx));
            }
            #pragma unroll
            for (int jj = 0; jj < 2; ++jj) {
                uint32_t n = (uint32_t)(wn * 32 + jj * 16 + (lane & 7) + ((lane & 16) >> 1));
                uint32_t k2 = (uint32_t)(kk * 16 + (lane & 8)) * 2;
                uint32_t r[4];
                ldsm4(r, aBase + 16384 + n * 128 + (k2 ^ swx));
                bf[jj * 2][0] = r[0]; bf[jj * 2][1] = r[1];
                bf[jj * 2 + 1][0] = r[2]; bf[jj * 2 + 1][1] = r[3];
            }
            #pragma unroll
            for (int i = 0; i < 2; ++i)
                #pragma unroll
                for (int j = 0; j < 4; ++j)
                    mma16816(acc[i][j], a[i], bf[j]);
        }
        __syncthreads();
        if (s < 2) prefetch(s + 2, s & 1);
        CP_COMMIT();
    }

    // ---------- fused epilogue ----------
    #pragma unroll
    for (int j = 0; j < 4; ++j) {
        int cl = wn * 32 + j * 8 + (lane & 3) * 2;
        int c0 = nTile + cl;
        float bs0 = bias[c0], bs1 = bias[c0 + 1];
        #pragma unroll
        for (int i = 0; i < 2; ++i) {
            #pragma unroll
            for (int half = 0; half < 2; ++half) {
                int m0 = rowBase + wm * 32 + i * 16 + (lane >> 2) + half * 8;
                if (m0 >= NN) continue;
                float v0 = acc[i][j][half * 2 + 0] + bs0;
                float v1 = acc[i][j][half * 2 + 1] + bs1;
                if (MODE == 0) {
                    if (c0 < 128) {
                        *(__half2*)(zP + (size_t)m0 * HD + c0) =
                            __float22half2_rn(make_float2(sigf(v0), sigf(v1)));
                    } else {
                        int n2 = c0 - 128;
                        float2 hv = __half22float2(*(__half2*)(hP + (size_t)m0 * HD + n2));
                        *(__half2*)(rhP + (size_t)m0 * HD + n2) =
                            __float22half2_rn(make_float2(sigf(v0) * hv.x, sigf(v1) * hv.y));
                    }
                } else {
                    float2 hv = __half22float2(*(__half2*)(hP + (size_t)m0 * HD + c0));
                    float2 zv = __half22float2(*(__half2*)(zP + (size_t)m0 * HD + c0));
                    float o0 = zv.x * hv.x + (1.f - zv.x) * tanhf(v0);
                    float o1 = zv.y * hv.y + (1.f - zv.y) * tanhf(v1);
                    *(__half2*)(hP + (size_t)m0 * HD + c0) =
                        __float22half2_rn(make_float2(o0, o1));
                    if (outF)
                        *(float2*)(outF + (size_t)m0 * HD + c0) = make_float2(o0, o1);
                }
            }
        }
    }
}

// ================= host =================
extern "C" void kernel_launch(void* const* d_in, const int* in_sizes, int n_in,
                              void* d_out, int out_size) {
    if (n_in < 15) return;
    const float* x   = (const float*)d_in[0];
    const float* h0  = (const float*)d_in[1];
    const int*   ei  = (const int*)  d_in[2];
    const float* Wxz = (const float*)d_in[3];
    const float* Whz = (const float*)d_in[4];
    const float* Wxr = (const float*)d_in[5];
    const float* Whr = (const float*)d_in[6];
    const float* Wxh = (const float*)d_in[7];
    const float* Whh = (const float*)d_in[8];
    const float* bxz = (const float*)d_in[9];
    const float* bhz = (const float*)d_in[10];
    const float* bxr = (const float*)d_in[11];
    const float* bhr = (const float*)d_in[12];
    const float* bxh = (const float*)d_in[13];
    const float* bhh = (const float*)d_in[14];
    float* out = (float*)d_out;

    float *p_bzr, *p_bh;
    __half *p_xf16, *p_hf16, *p_z0, *p_z1, *p_rhf16, *p_aX, *p_aY, *p_aH0, *p_aR, *p_Bzr, *p_Bh;
    cudaGetSymbolAddress((void**)&p_xf16,  g_xf16);
    cudaGetSymbolAddress((void**)&p_hf16,  g_hf16);
    cudaGetSymbolAddress((void**)&p_z0,    g_z0);
    cudaGetSymbolAddress((void**)&p_z1,    g_z1);
    cudaGetSymbolAddress((void**)&p_rhf16, g_rhf16);
    cudaGetSymbolAddress((void**)&p_aX,    g_aX);
    cudaGetSymbolAddress((void**)&p_aY,    g_aY);
    cudaGetSymbolAddress((void**)&p_aH0,   g_aH0);
    cudaGetSymbolAddress((void**)&p_aR,    g_aR);
    cudaGetSymbolAddress((void**)&p_Bzr,   g_Bzr);
    cudaGetSymbolAddress((void**)&p_Bh,    g_Bh);
    cudaGetSymbolAddress((void**)&p_bzr,   g_bzr);
    cudaGetSymbolAddress((void**)&p_bh,    g_bh);

    cudaFuncSetAttribute((const void*)k_mma_gemm<0>,
                         cudaFuncAttributeMaxDynamicSharedMemorySize, SMEM_GEMM);
    cudaFuncSetAttribute((const void*)k_mma_gemm<1>,
                         cudaFuncAttributeMaxDynamicSharedMemorySize, SMEM_GEMM);

    static cudaStream_t s2 = nullptr;
    static cudaEvent_t evS = nullptr, evI = nullptr, e1 = nullptr, e2 = nullptr,
                       e3 = nullptr, evF = nullptr, evG = nullptr;
    if (!s2) {
        cudaStreamCreateWithFlags(&s2, cudaStreamNonBlocking);
        cudaEventCreateWithFlags(&evS, cudaEventDisableTiming);
        cudaEventCreateWithFlags(&evI, cudaEventDisableTiming);
        cudaEventCreateWithFlags(&e1,  cudaEventDisableTiming);
        cudaEventCreateWithFlags(&e2,  cudaEventDisableTiming);
        cudaEventCreateWithFlags(&e3,  cudaEventDisableTiming);
        cudaEventCreateWithFlags(&evF, cudaEventDisableTiming);
        cudaEventCreateWithFlags(&evG, cudaEventDisableTiming);
    }

    const int NB = (NN + 1023) / 1024;
    const int spmm_blocks = (NN + 7) / 8;
    const int gM = (NN + 127) / 128;  // 391

    // ---- setup: fork k_init onto s2, CSR build on main ----
    k_zero<<<(NN + 255) / 256, 256>>>();
    cudaEventRecord(evS, 0);
    cudaStreamWaitEvent(s2, evS, 0);
    {
        int tot = NL * 256 * 256 + NL * 128 * 256 + NL * 256 + NL * 128
                + NL * NN * HD / 4 + NT * NN * HD / 4;
        k_init<<<(tot + 255) / 256, 256, 0, s2>>>(Wxz, Whz, Wxr, Whr, Wxh, Whh,
                                                  bxz, bhz, bxr, bhr, bxh, bhh,
                                                  (const float4*)h0, (const float4*)x);
    }
    cudaEventRecord(evI, s2);
    k_count<<<(NE + 255) / 256, 256>>>(ei);
    k_scan1<<<NB, 1024>>>();
    k_scan2<<<1, 64>>>();
    k_scan3<<<NB, 1024>>>();
    k_fill<<<(NE + 255) / 256, 256>>>(ei);
    cudaStreamWaitEvent(0, evI, 0);

    __half* h0_16 = p_hf16;
    __half* h1_16 = p_hf16 + (size_t)NN * HD;

    // prologue: aX = A@x_0, aH0 = A@h0_init
    k_spmm2<<<spmm_blocks, 256>>>(p_xf16, h0_16, p_aX, p_aH0);

    for (int t = 0; t < NT; ++t) {
        // A_rh: gemm0 L0 rh-half (main)
        k_mma_gemm<0><<<dim3(gM, 2), 256, SMEM_GEMM>>>(
            p_aX, p_aH0, p_Bzr, p_bzr, h0_16, p_z0, p_rhf16, nullptr, 128);
        cudaEventRecord(e1, 0);
        cudaStreamWaitEvent(s2, e1, 0);
        // A_z on s2 (writes z0) — overlaps spmm B
        k_mma_gemm<0><<<dim3(gM, 2), 256, SMEM_GEMM, s2>>>(
            p_aX, p_aH0, p_Bzr, p_bzr, h0_16, p_z0, p_rhf16, nullptr, 0);
        cudaEventRecord(e2, s2);
        // B: spmm(rh)->aR; waits G(t-1) which read aR
        if (t > 0) cudaStreamWaitEvent(0, evG, 0);
        k_spmm<<<spmm_blocks, 256>>>(p_rhf16, p_aR);
        cudaStreamWaitEvent(0, e2, 0);      // z0 ready; orders A_z reads before D/F writes
        // C: gemm1 L0 -> h0
        k_mma_gemm<1><<<dim3(gM, 2), 256, SMEM_GEMM>>>(
            p_aX, p_aR, p_Bh, p_bh, h0_16, p_z0, nullptr, nullptr, 0);
        // D: spmm2(h0, h1) -> aH0, aY
        k_spmm2<<<spmm_blocks, 256>>>(h0_16, h1_16, p_aH0, p_aY);
        // E_rh: gemm0 L1 rh-half (main)
        k_mma_gemm<0><<<dim3(gM, 2), 256, SMEM_GEMM>>>(
            p_aH0, p_aY, p_Bzr + 256 * 256, p_bzr + 256,
            h1_16, p_z1, p_rhf16, nullptr, 128);
        cudaEventRecord(e3, 0);
        cudaStreamWaitEvent(s2, e3, 0);
        // E_z on s2 (writes z1) — overlaps spmm2 F
        k_mma_gemm<0><<<dim3(gM, 2), 256, SMEM_GEMM, s2>>>(
            p_aH0, p_aY, p_Bzr + 256 * 256, p_bzr + 256,
            h1_16, p_z1, p_rhf16, nullptr, 0);
        // F: spmm2(rh, x_{t+1}) -> aR, aX  (folds next-step x aggregation)
        if (t + 1 < NT) {
            k_spmm2<<<spmm_blocks, 256>>>(p_rhf16, p_xf16 + (size_t)(t + 1) * NN * HD,
                                          p_aR, p_aX);
        } else {
            k_spmm<<<spmm_blocks, 256>>>(p_rhf16, p_aR);
        }
        // G: gemm1 L1 -> h1, out on s2 (after E_z in-order; waits F for aR); overlaps A_rh(t+1)
        cudaEventRecord(evF, 0);
        cudaStreamWaitEvent(s2, evF, 0);
        k_mma_gemm<1><<<dim3(gM, 2), 256, SMEM_GEMM, s2>>>(
            p_aH0, p_aR, p_Bh + 128 * 256, p_bh + 128,
            h1_16, p_z1, nullptr, out + (size_t)t * NN * HD, 0);
        cudaEventRecord(evG, s2);
    }
    cudaStreamWaitEvent(0, evG, 0);
}

// round 16
// speedup vs baseline: 1.4746x; 1.0455x over previous
#include <cuda_runtime.h>
#include <cuda_fp16.h>
#include <math.h>
#include <stdint.h>

#define NT 8
#define NN 50000
#define NE 800000
#define HD 128
#define NL 2

__device__ __forceinline__ uint32_t smem_u32(const void* p) {
    uint32_t a;
    asm("{ .reg .u64 t; cvta.to.shared.u64 t, %1; cvt.u32.u64 %0, t; }" : "=r"(a) : "l"(p));
    return a;
}
__device__ __forceinline__ float sigf(float x) { return 1.f / (1.f + __expf(-x)); }

__device__ __forceinline__ void mma16816(float* d, const uint32_t* a, const uint32_t* b) {
    asm volatile("mma.sync.aligned.m16n8k16.row.col.f32.f16.f16.f32 "
        "{%0,%1,%2,%3}, {%4,%5,%6,%7}, {%8,%9}, {%0,%1,%2,%3};"
        : "+f"(d[0]), "+f"(d[1]), "+f"(d[2]), "+f"(d[3])
        : "r"(a[0]), "r"(a[1]), "r"(a[2]), "r"(a[3]), "r"(b[0]), "r"(b[1]));
}
__device__ __forceinline__ void ldsm4(uint32_t* r, uint32_t addr) {
    asm volatile("ldmatrix.sync.aligned.m8n8.x4.shared.b16 {%0,%1,%2,%3}, [%4];"
        : "=r"(r[0]), "=r"(r[1]), "=r"(r[2]), "=r"(r[3]) : "r"(addr));
}
__device__ __forceinline__ void cpa16(uint32_t dst, const void* src, bool pred) {
    asm volatile("cp.async.cg.shared.global [%0], [%1], 16, %2;"
        :: "r"(dst), "l"(__cvta_generic_to_global(src)), "r"(pred ? 16 : 0) : "memory");
}
#define CP_COMMIT() asm volatile("cp.async.commit_group;" ::: "memory")
#define CP_WAIT1()  asm volatile("cp.async.wait_group 1;" ::: "memory")

// streaming store (evict-first): out is write-once, never re-read
__device__ __forceinline__ void stcs2(float* p, float x, float y) {
    asm volatile("st.global.cs.v2.f32 [%0], {%1, %2};"
        :: "l"(__cvta_generic_to_global(p)), "f"(x), "f"(y) : "memory");
}

__device__ __forceinline__ uint2 packh4(float4 a) {
    __half2 p0 = __float22half2_rn(make_float2(a.x, a.y));
    __half2 p1 = __float22half2_rn(make_float2(a.z, a.w));
    uint2 r;
    r.x = *(uint32_t*)&p0;
    r.y = *(uint32_t*)&p1;
    return r;
}
__device__ __forceinline__ void acc8(float* a, uint4 u, float w) {
    float2 f;
    f = __half22float2(*(__half2*)&u.x); a[0] += w * f.x; a[1] += w * f.y;
    f = __half22float2(*(__half2*)&u.y); a[2] += w * f.x; a[3] += w * f.y;
    f = __half22float2(*(__half2*)&u.z); a[4] += w * f.x; a[5] += w * f.y;
    f = __half22float2(*(__half2*)&u.w); a[6] += w * f.x; a[7] += w * f.y;
}
__device__ __forceinline__ uint4 pack8(const float* a) {
    uint4 r;
    __half2 h;
    h = __float22half2_rn(make_float2(a[0], a[1])); r.x = *(uint32_t*)&h;
    h = __float22half2_rn(make_float2(a[2], a[3])); r.y = *(uint32_t*)&h;
    h = __float22half2_rn(make_float2(a[4], a[5])); r.z = *(uint32_t*)&h;
    h = __float22half2_rn(make_float2(a[6], a[7])); r.w = *(uint32_t*)&h;
    return r;
}

// ================= static device scratch =================
__device__ __align__(128) __half g_xf16[NT * NN * HD];
__device__ __align__(128) __half g_hf16[NL][NN * HD];
__device__ __align__(128) __half g_z0[NN * HD];
__device__ __align__(128) __half g_z1[NN * HD];
__device__ __align__(128) __half g_rhf16[NN * HD];
__device__ __align__(128) __half g_aX[NN * HD];
__device__ __align__(128) __half g_aY[NN * HD];
__device__ __align__(128) __half g_aH0[NN * HD];
__device__ __align__(128) __half g_aR[NN * HD];
__device__ int   g_cnt[NN];
__device__ int   g_cur[NN];
__device__ int   g_offs[NN + 1];
__device__ float g_dinv[NN];
__device__ int2  g_epack[NE];
__device__ int   g_bsum[64];
__device__ int   g_bbase[64];
__device__ __align__(128) __half g_Bzr[NL * 256 * 256];
__device__ __align__(128) __half g_Bh [NL * 128 * 256];
__device__ float g_bzr[NL][256];
__device__ float g_bh [NL][128];

// ================= setup kernels =================
__global__ void k_zero() {
    int i = blockIdx.x * blockDim.x + threadIdx.x;
    if (i < NN) { g_cnt[i] = 0; g_cur[i] = 0; }
}
__global__ void k_count(const int* __restrict__ ei) {
    int e = blockIdx.x * blockDim.x + threadIdx.x;
    if (e < NE) atomicAdd(&g_cnt[ei[e]], 1);
}
__global__ void k_scan1() {
    __shared__ int s[1024];
    int t = threadIdx.x;
    int i = blockIdx.x * 1024 + t;
    int v = (i < NN) ? g_cnt[i] : 0;
    if (i < NN) g_dinv[i] = rsqrtf((float)(v + 2));
    s[t] = v; __syncthreads();
    #pragma unroll
    for (int off = 1; off < 1024; off <<= 1) {
        int x = (t >= off) ? s[t - off] : 0;
        __syncthreads(); s[t] += x; __syncthreads();
    }
    if (i < NN) g_offs[i] = s[t] - v;
    if (t == 1023) g_bsum[blockIdx.x] = s[1023];
}
__global__ void k_scan2() {
    __shared__ int s[64];
    int t = threadIdx.x;
    const int NB = (NN + 1023) / 1024;
    int v = (t < NB) ? g_bsum[t] : 0;
    s[t] = v; __syncthreads();
    #pragma unroll
    for (int off = 1; off < 64; off <<= 1) {
        int x = (t >= off) ? s[t - off] : 0;
        __syncthreads(); s[t] += x; __syncthreads();
    }
    if (t < NB) g_bbase[t] = s[t] - v;
    if (t == 63) g_offs[NN] = s[63];
}
__global__ void k_scan3() {
    int i = blockIdx.x * 1024 + threadIdx.x;
    if (i < NN) g_offs[i] += g_bbase[blockIdx.x];
}
__global__ void k_fill(const int* __restrict__ ei) {
    int e = blockIdx.x * blockDim.x + threadIdx.x;
    if (e < NE) {
        int r = ei[e];
        int c = ei[NE + e];
        int pos = g_offs[r] + atomicAdd(&g_cur[r], 1);
        g_epack[pos] = make_int2(c, __float_as_int(g_dinv[r] * g_dinv[c]));
    }
}
__global__ void k_init(const float* __restrict__ Wxz, const float* __restrict__ Whz,
                       const float* __restrict__ Wxr, const float* __restrict__ Whr,
                       const float* __restrict__ Wxh, const float* __restrict__ Whh,
                       const float* __restrict__ bxz, const float* __restrict__ bhz,
                       const float* __restrict__ bxr, const float* __restrict__ bhr,
                       const float* __restrict__ bxh, const float* __restrict__ bhh,
                       const float4* __restrict__ h0, const float4* __restrict__ x) {
    int i = blockIdx.x * blockDim.x + threadIdx.x;
    const int ZR = NL * 256 * 256;
    const int HS = NL * 128 * 256;
    const int B1 = ZR + HS;
    const int B2 = B1 + NL * 256;
    const int B3 = B2 + NL * 128;
    const int CP = NL * NN * HD / 4;
    const int B4 = B3 + CP;
    const int XC = NT * NN * HD / 4;
    if (i < ZR) {
        int l = i / (256 * 256);
        int nk = i % (256 * 256);
        int n = nk / 256, k = nk % 256;
        const float* W = (k < 128) ? ((n < 128) ? Wxz : Wxr)
                                   : ((n < 128) ? Whz : Whr);
        g_Bzr[l * 256 * 256 + nk] =
            __float2half_rn(W[l * HD * HD + (k & 127) * HD + (n & 127)]);
    } else if (i < B1) {
        int i2 = i - ZR;
        int l = i2 / (128 * 256);
        int nk = i2 % (128 * 256);
        int n = nk / 256, k = nk % 256;
        const float* W = (k < 128) ? Wxh : Whh;
        g_Bh[l * 128 * 256 + nk] =
            __float2half_rn(W[l * HD * HD + (k & 127) * HD + n]);
    } else if (i < B2) {
        int i2 = i - B1;
        int l = i2 / 256, j = i2 % 256;
        g_bzr[l][j] = (j < 128) ? (bxz[l * HD + j] + bhz[l * HD + j])
                                : (bxr[l * HD + j - 128] + bhr[l * HD + j - 128]);
    } else if (i < B3) {
        int i2 = i - B2;
        int l = i2 / 128, j = i2 % 128;
        g_bh[l][j] = bxh[l * HD + j] + bhh[l * HD + j];
    } else if (i < B4) {
        int j = i - B3;
        ((uint2*)&g_hf16[0][0])[j] = packh4(h0[j]);
    } else if (i - B4 < XC) {
        int j = i - B4;
        ((uint2*)&g_xf16[0])[j] = packh4(x[j]);
    }
}

// ================= SpMM: half-warp per edge, 2 edges/warp/iter (R10 proven) ==========
__global__ void __launch_bounds__(256) k_spmm2(
    const __half* __restrict__ srcA, const __half* __restrict__ srcB,
    __half* __restrict__ oA, __half* __restrict__ oB) {
    int row = (blockIdx.x * blockDim.x + threadIdx.x) >> 5;
    int lane = threadIdx.x & 31;
    if (row >= NN) return;
    int hw = lane >> 4, sl = lane & 15;
    const uint4* sA = (const uint4*)srcA;
    const uint4* sB = (const uint4*)srcB;
    float aA[8], aB[8];
    #pragma unroll
    for (int k = 0; k < 8; ++k) { aA[k] = 0.f; aB[k] = 0.f; }
    int e0 = g_offs[row], end = g_offs[row + 1];
    #pragma unroll 4
    for (int e = e0 + hw; e < end; e += 2) {
        int2 ew = g_epack[e];
        float w = __int_as_float(ew.y);
        uint4 u = sA[(size_t)ew.x * 16 + sl];
        uint4 v = sB[(size_t)ew.x * 16 + sl];
        acc8(aA, u, w);
        acc8(aB, v, w);
    }
    #pragma unroll
    for (int k = 0; k < 8; ++k) {
        aA[k] += __shfl_xor_sync(0xffffffff, aA[k], 16);
        aB[k] += __shfl_xor_sync(0xffffffff, aB[k], 16);
    }
    if (hw == 0) {
        float di = g_dinv[row];
        float ws = 2.f * di * di;
        acc8(aA, sA[(size_t)row * 16 + sl], ws);
        acc8(aB, sB[(size_t)row * 16 + sl], ws);
        ((uint4*)oA)[(size_t)row * 16 + sl] = pack8(aA);
        ((uint4*)oB)[(size_t)row * 16 + sl] = pack8(aB);
    }
}

__global__ void __launch_bounds__(256) k_spmm(const __half* __restrict__ src,
                                              __half* __restrict__ o) {
    int row = (blockIdx.x * blockDim.x + threadIdx.x) >> 5;
    int lane = threadIdx.x & 31;
    if (row >= NN) return;
    int hw = lane >> 4, sl = lane & 15;
    const uint4* s4 = (const uint4*)src;
    float a[8];
    #pragma unroll
    for (int k = 0; k < 8; ++k) a[k] = 0.f;
    int e0 = g_offs[row], end = g_offs[row + 1];
    #pragma unroll 4
    for (int e = e0 + hw; e < end; e += 2) {
        int2 ew = g_epack[e];
        float w = __int_as_float(ew.y);
        acc8(a, s4[(size_t)ew.x * 16 + sl], w);
    }
    #pragma unroll
    for (int k = 0; k < 8; ++k)
        a[k] += __shfl_xor_sync(0xffffffff, a[k], 16);
    if (hw == 0) {
        float di = g_dinv[row];
        acc8(a, s4[(size_t)row * 16 + sl], 2.f * di * di);
        ((uint4*)o)[(size_t)row * 16 + sl] = pack8(a);
    }
}

// ================= pipelined HMMA GEMM, NCOL=64 tiles, 4x2 warp grid (R10) =========
#define STAGE_SZ 24576
#define SMEM_GEMM (2 * STAGE_SZ)

template <int MODE>
__global__ void __launch_bounds__(256) k_mma_gemm(
    const __half* __restrict__ Ax, const __half* __restrict__ Ay,
    const __half* __restrict__ B, const float* __restrict__ bias,
    __half* __restrict__ hP, __half* __restrict__ zP,
    __half* __restrict__ rhP, float* __restrict__ outF, int nBase) {

    extern __shared__ char smem[];
    uint32_t sb = smem_u32(smem);
    int tid = threadIdx.x;
    int lane = tid & 31, warp = tid >> 5;
    int wm = warp >> 1;
    int wn = warp & 1;
    int rowBase = blockIdx.x * 128;
    int nTile = nBase + blockIdx.y * 64;

    float acc[2][4][4];
    #pragma unroll
    for (int i = 0; i < 2; ++i)
        #pragma unroll
        for (int j = 0; j < 4; ++j)
            #pragma unroll
            for (int q = 0; q < 4; ++q) acc[i][j][q] = 0.f;

    const uint32_t swx = (uint32_t)(lane & 7) << 4;

    auto prefetch = [&](int s, int b) {
        const __half* Ap = (s < 2) ? Ax : Ay;
        int ka = (s & 1) * 64;
        int kb = s * 64;
        uint32_t base = sb + (uint32_t)b * STAGE_SZ;
        #pragma unroll
        for (int u = 0; u < 4; ++u) {
            int idx = u * 256 + tid;
            int row = idx >> 3, c = idx & 7;
            uint32_t soff = (uint32_t)row * 128 +
                            (((uint32_t)c * 16) ^ (((uint32_t)row & 7) << 4));
            int gm = rowBase + row;
            cpa16(base + soff, Ap + (size_t)gm * HD + ka + c * 8, gm < NN);
        }
        #pragma unroll
        for (int u = 0; u < 2; ++u) {
            int idx = u * 256 + tid;
            int row = idx >> 3, c = idx & 7;
            uint32_t soff = (uint32_t)row * 128 +
                            (((uint32_t)c * 16) ^ (((uint32_t)row & 7) << 4));
            int gn = nTile + row;
            cpa16(base + 16384 + soff, B + (size_t)gn * 256 + kb + c * 8, true);
        }
    };

    prefetch(0, 0); CP_COMMIT();
    prefetch(1, 1); CP_COMMIT();

    #pragma unroll 1
    for (int s = 0; s < 4; ++s) {
        CP_WAIT1();
        __syncthreads();
        uint32_t aBase = sb + (uint32_t)(s & 1) * STAGE_SZ;
        #pragma unroll
        for (int kk = 0; kk < 4; ++kk) {
            uint32_t a[2][4], bf[4][2];
            #pragma unroll
            for (int i = 0; i < 2; ++i) {
                uint32_t m = (uint32_t)(wm * 32 + i * 16 + (lane & 15));
                uint32_t k2 = (uint32_t)(kk * 16 + ((lane & 16) >> 1)) * 2;
                ldsm4(a[i], aBase + m * 128 + (k2 ^ swx));
            }
            #pragma unroll
            for (int jj = 0; jj < 2; ++jj) {
                uint32_t n = (uint32_t)(wn * 32 + jj * 16 + (lane & 7) + ((lane & 16) >> 1));
                uint32_t k2 = (uint32_t)(kk * 16 + (lane & 8)) * 2;
                uint32_t r[4];
                ldsm4(r, aBase + 16384 + n * 128 + (k2 ^ swx));
                bf[jj * 2][0] = r[0]; bf[jj * 2][1] = r[1];
                bf[jj * 2 + 1][0] = r[2]; bf[jj * 2 + 1][1] = r[3];
            }
            #pragma unroll
            for (int i = 0; i < 2; ++i)
                #pragma unroll
                for (int j = 0; j < 4; ++j)
                    mma16816(acc[i][j], a[i], bf[j]);
        }
        __syncthreads();
        if (s < 2) prefetch(s + 2, s & 1);
        CP_COMMIT();
    }

    // ---------- fused epilogue ----------
    #pragma unroll
    for (int j = 0; j < 4; ++j) {
        int cl = wn * 32 + j * 8 + (lane & 3) * 2;
        int c0 = nTile + cl;
        float bs0 = bias[c0], bs1 = bias[c0 + 1];
        #pragma unroll
        for (int i = 0; i < 2; ++i) {
            #pragma unroll
            for (int half = 0; half < 2; ++half) {
                int m0 = rowBase + wm * 32 + i * 16 + (lane >> 2) + half * 8;
                if (m0 >= NN) continue;
                float v0 = acc[i][j][half * 2 + 0] + bs0;
                float v1 = acc[i][j][half * 2 + 1] + bs1;
                if (MODE == 0) {
                    if (c0 < 128) {
                        *(__half2*)(zP + (size_t)m0 * HD + c0) =
                            __float22half2_rn(make_float2(sigf(v0), sigf(v1)));
                    } else {
                        int n2 = c0 - 128;
                        float2 hv = __half22float2(*(__half2*)(hP + (size_t)m0 * HD + n2));
                        *(__half2*)(rhP + (size_t)m0 * HD + n2) =
                            __float22half2_rn(make_float2(sigf(v0) * hv.x, sigf(v1) * hv.y));
                    }
                } else {
                    float2 hv = __half22float2(*(__half2*)(hP + (size_t)m0 * HD + c0));
                    float2 zv = __half22float2(*(__half2*)(zP + (size_t)m0 * HD + c0));
                    float o0 = zv.x * hv.x + (1.f - zv.x) * tanhf(v0);
                    float o1 = zv.y * hv.y + (1.f - zv.y) * tanhf(v1);
                    *(__half2*)(hP + (size_t)m0 * HD + c0) =
                        __float22half2_rn(make_float2(o0, o1));
                    if (outF)
                        stcs2(outF + (size_t)m0 * HD + c0, o0, o1);
                }
            }
        }
    }
}

// ================= host =================
extern "C" void kernel_launch(void* const* d_in, const int* in_sizes, int n_in,
                              void* d_out, int out_size) {
    if (n_in < 15) return;
    const float* x   = (const float*)d_in[0];
    const float* h0  = (const float*)d_in[1];
    const int*   ei  = (const int*)  d_in[2];
    const float* Wxz = (const float*)d_in[3];
    const float* Whz = (const float*)d_in[4];
    const float* Wxr = (const float*)d_in[5];
    const float* Whr = (const float*)d_in[6];
    const float* Wxh = (const float*)d_in[7];
    const float* Whh = (const float*)d_in[8];
    const float* bxz = (const float*)d_in[9];
    const float* bhz = (const float*)d_in[10];
    const float* bxr = (const float*)d_in[11];
    const float* bhr = (const float*)d_in[12];
    const float* bxh = (const float*)d_in[13];
    const float* bhh = (const float*)d_in[14];
    float* out = (float*)d_out;

    float *p_bzr, *p_bh;
    __half *p_xf16, *p_hf16, *p_z0, *p_z1, *p_rhf16, *p_aX, *p_aY, *p_aH0, *p_aR, *p_Bzr, *p_Bh;
    cudaGetSymbolAddress((void**)&p_xf16,  g_xf16);
    cudaGetSymbolAddress((void**)&p_hf16,  g_hf16);
    cudaGetSymbolAddress((void**)&p_z0,    g_z0);
    cudaGetSymbolAddress((void**)&p_z1,    g_z1);
    cudaGetSymbolAddress((void**)&p_rhf16, g_rhf16);
    cudaGetSymbolAddress((void**)&p_aX,    g_aX);
    cudaGetSymbolAddress((void**)&p_aY,    g_aY);
    cudaGetSymbolAddress((void**)&p_aH0,   g_aH0);
    cudaGetSymbolAddress((void**)&p_aR,    g_aR);
    cudaGetSymbolAddress((void**)&p_Bzr,   g_Bzr);
    cudaGetSymbolAddress((void**)&p_Bh,    g_Bh);
    cudaGetSymbolAddress((void**)&p_bzr,   g_bzr);
    cudaGetSymbolAddress((void**)&p_bh,    g_bh);

    cudaFuncSetAttribute((const void*)k_mma_gemm<0>,
                         cudaFuncAttributeMaxDynamicSharedMemorySize, SMEM_GEMM);
    cudaFuncSetAttribute((const void*)k_mma_gemm<1>,
                         cudaFuncAttributeMaxDynamicSharedMemorySize, SMEM_GEMM);

    static cudaStream_t s2 = nullptr;
    static cudaEvent_t evS = nullptr, evI = nullptr, e1 = nullptr, e2 = nullptr,
                       e3 = nullptr, evF = nullptr, evG = nullptr;
    if (!s2) {
        cudaStreamCreateWithFlags(&s2, cudaStreamNonBlocking);
        cudaEventCreateWithFlags(&evS, cudaEventDisableTiming);
        cudaEventCreateWithFlags(&evI, cudaEventDisableTiming);
        cudaEventCreateWithFlags(&e1,  cudaEventDisableTiming);
        cudaEventCreateWithFlags(&e2,  cudaEventDisableTiming);
        cudaEventCreateWithFlags(&e3,  cudaEventDisableTiming);
        cudaEventCreateWithFlags(&evF, cudaEventDisableTiming);
        cudaEventCreateWithFlags(&evG, cudaEventDisableTiming);
    }

    const int NB = (NN + 1023) / 1024;
    const int spmm_blocks = (NN + 7) / 8;
    const int gM = (NN + 127) / 128;  // 391

    // ---- setup: fork k_init onto s2, CSR build on main ----
    k_zero<<<(NN + 255) / 256, 256>>>();
    cudaEventRecord(evS, 0);
    cudaStreamWaitEvent(s2, evS, 0);
    {
        int tot = NL * 256 * 256 + NL * 128 * 256 + NL * 256 + NL * 128
                + NL * NN * HD / 4 + NT * NN * HD / 4;
        k_init<<<(tot + 255) / 256, 256, 0, s2>>>(Wxz, Whz, Wxr, Whr, Wxh, Whh,
                                                  bxz, bhz, bxr, bhr, bxh, bhh,
                                                  (const float4*)h0, (const float4*)x);
    }
    cudaEventRecord(evI, s2);
    k_count<<<(NE + 255) / 256, 256>>>(ei);
    k_scan1<<<NB, 1024>>>();
    k_scan2<<<1, 64>>>();
    k_scan3<<<NB, 1024>>>();
    k_fill<<<(NE + 255) / 256, 256>>>(ei);
    cudaStreamWaitEvent(0, evI, 0);

    __half* h0_16 = p_hf16;
    __half* h1_16 = p_hf16 + (size_t)NN * HD;

    // prologue: aX = A@x_0, aH0 = A@h0_init
    k_spmm2<<<spmm_blocks, 256>>>(p_xf16, h0_16, p_aX, p_aH0);

    for (int t = 0; t < NT; ++t) {
        // A_rh: gemm0 L0 rh-half (main)
        k_mma_gemm<0><<<dim3(gM, 2), 256, SMEM_GEMM>>>(
            p_aX, p_aH0, p_Bzr, p_bzr, h0_16, p_z0, p_rhf16, nullptr, 128);
        cudaEventRecord(e1, 0);
        cudaStreamWaitEvent(s2, e1, 0);
        // A_z on s2 (writes z0) — overlaps spmm B
        k_mma_gemm<0><<<dim3(gM, 2), 256, SMEM_GEMM, s2>>>(
            p_aX, p_aH0, p_Bzr, p_bzr, h0_16, p_z0, p_rhf16, nullptr, 0);
        cudaEventRecord(e2, s2);
        // B: spmm(rh)->aR; waits G(t-1) which read aR
        if (t > 0) cudaStreamWaitEvent(0, evG, 0);
        k_spmm<<<spmm_blocks, 256>>>(p_rhf16, p_aR);
        cudaStreamWaitEvent(0, e2, 0);      // z0 ready; orders A_z reads before D/F writes
        // C: gemm1 L0 -> h0
        k_mma_gemm<1><<<dim3(gM, 2), 256, SMEM_GEMM>>>(
            p_aX, p_aR, p_Bh, p_bh, h0_16, p_z0, nullptr, nullptr, 0);
        // D: spmm2(h0, h1) -> aH0, aY
        k_spmm2<<<spmm_blocks, 256>>>(h0_16, h1_16, p_aH0, p_aY);
        // E_rh: gemm0 L1 rh-half (main)
        k_mma_gemm<0><<<dim3(gM, 2), 256, SMEM_GEMM>>>(
            p_aH0, p_aY, p_Bzr + 256 * 256, p_bzr + 256,
            h1_16, p_z1, p_rhf16, nullptr, 128);
        cudaEventRecord(e3, 0);
        cudaStreamWaitEvent(s2, e3, 0);
        // E_z on s2 (writes z1) — overlaps spmm2 F
        k_mma_gemm<0><<<dim3(gM, 2), 256, SMEM_GEMM, s2>>>(
            p_aH0, p_aY, p_Bzr + 256 * 256, p_bzr + 256,
            h1_16, p_z1, p_rhf16, nullptr, 0);
        // F: spmm2(rh, x_{t+1}) -> aR, aX  (folds next-step x aggregation)
        if (t + 1 < NT) {
            k_spmm2<<<spmm_blocks, 256>>>(p_rhf16, p_xf16 + (size_t)(t + 1) * NN * HD,
                                          p_aR, p_aX);
        } else {
            k_spmm<<<spmm_blocks, 256>>>(p_rhf16, p_aR);
        }
        // G: gemm1 L1 -> h1, out on s2 (after E_z in-order; waits F for aR); overlaps A_rh(t+1)
        cudaEventRecord(evF, 0);
        cudaStreamWaitEvent(s2, evF, 0);
        k_mma_gemm<1><<<dim3(gM, 2), 256, SMEM_GEMM, s2>>>(
            p_aH0, p_aR, p_Bh + 128 * 256, p_bh + 128,
            h1_16, p_z1, nullptr, out + (size_t)t * NN * HD, 0);
        cudaEventRecord(evG, s2);
    }
    cudaStreamWaitEvent(0, evG, 0);
}